// round 1
// baseline (speedup 1.0000x reference)
#include <cuda_runtime.h>
#include <cuda_bf16.h>
#include <math.h>

#define NN 4096
#define DD 256
#define KK 32
#define LL 4
#define TT 100
#define PP 64
#define BB 32
#define CIN 420   // T + D + P
#define NSTATE 5  // L+1

// ---------------- scratch (device globals; no allocations) ----------------
__device__ float g_in[NN * CIN];
__device__ float g_t0[NN * DD];          // gemm output before LN
__device__ float g_h[NN * DD];           // current h (post-LN, masked)
__device__ float g_hs[NN * DD];          // layernorm(h @ W_self)
__device__ float g_msg[NN * DD];         // mean message
__device__ float g_agg[NN * DD];         // msg @ W_conv
__device__ float g_states[NN * NSTATE * DD];
__device__ float g_out[NN * DD];         // states @ W_out
__device__ int   g_idx[NN * KK];
__device__ float g_ed[NN * KK];
__device__ float g_rbf[NN * KK * BB];

// ---------------- input build: concat(time_embed*mask, feat, pos) ----------------
__global__ void build_in_kernel(const float* __restrict__ feat,
                                const float* __restrict__ pos,
                                const float* __restrict__ mask,
                                const float* __restrict__ tptr,
                                float* __restrict__ out) {
    int i = blockIdx.x;
    float t = *tptr;
    float mk = mask[i];
    for (int c = threadIdx.x; c < CIN; c += blockDim.x) {
        float v;
        if (c < TT) {
            // centers = linspace(0,1,100); step = 1/99; d = (t - c_j)/step
            float d = (t - (float)c * (1.0f / 99.0f)) * 99.0f;
            float a = fabsf(d);
            if (a < 1.0f) {
                float cc = cospif(0.5f * d);
                v = cc * cc * mk;
            } else {
                v = 0.0f;
            }
        } else if (c < TT + DD) {
            v = feat[i * DD + (c - TT)];
        } else {
            v = pos[i * PP + (c - TT - DD)];
        }
        out[i * CIN + c] = v;
    }
}

// ---------------- layernorm over D=256, one block per row ----------------
__global__ __launch_bounds__(DD) void ln_kernel(const float* __restrict__ X,
                                                float* __restrict__ Y,
                                                const float* __restrict__ mask,
                                                float* __restrict__ states,
                                                int state_col) {
    int i = blockIdx.x;
    int tid = threadIdx.x;
    float x = X[i * DD + tid];
    __shared__ float red[8];
    // mean
    float s = x;
    #pragma unroll
    for (int o = 16; o > 0; o >>= 1) s += __shfl_down_sync(0xFFFFFFFFu, s, o);
    if ((tid & 31) == 0) red[tid >> 5] = s;
    __syncthreads();
    float tot = 0.0f;
    if (tid < 8) tot = red[tid];
    #pragma unroll
    for (int o = 4; o > 0; o >>= 1) tot += __shfl_down_sync(0xFFu, tot, o);
    __shared__ float mean_s, var_s;
    if (tid == 0) mean_s = tot * (1.0f / DD);
    __syncthreads();
    float m = mean_s;
    float dv = x - m;
    float s2 = dv * dv;
    #pragma unroll
    for (int o = 16; o > 0; o >>= 1) s2 += __shfl_down_sync(0xFFFFFFFFu, s2, o);
    if ((tid & 31) == 0) red[tid >> 5] = s2;
    __syncthreads();
    float tot2 = 0.0f;
    if (tid < 8) tot2 = red[tid];
    #pragma unroll
    for (int o = 4; o > 0; o >>= 1) tot2 += __shfl_down_sync(0xFFu, tot2, o);
    if (tid == 0) var_s = tot2 * (1.0f / DD);
    __syncthreads();
    float y = dv * rsqrtf(var_s + 1e-5f);
    if (mask) y *= mask[i];
    Y[i * DD + tid] = y;
    if (states) states[(size_t)i * (NSTATE * DD) + state_col * DD + tid] = y;
}

// ---------------- kNN: block per row, iterative argmin (tie -> smallest idx) ----------------
__global__ __launch_bounds__(256) void knn_kernel(const float* __restrict__ coord,
                                                  int* __restrict__ idx_out,
                                                  float* __restrict__ ed_out) {
    __shared__ float dist[NN];
    __shared__ float rv[256];
    __shared__ int ri[256];
    int i = blockIdx.x;
    int tid = threadIdx.x;
    float cx = coord[i * 3 + 0];
    float cy = coord[i * 3 + 1];
    float cz = coord[i * 3 + 2];
    for (int j = tid; j < NN; j += 256) {
        float dx = cx - coord[j * 3 + 0];
        float dy = cy - coord[j * 3 + 1];
        float dz = cz - coord[j * 3 + 2];
        float d2 = dx * dx + dy * dy + dz * dz;
        if (j == i) d2 += 1e9f;
        dist[j] = d2;
    }
    __syncthreads();
    for (int kk = 0; kk < KK; kk++) {
        float best = 3.4e38f;
        int bi = 0x7FFFFFFF;
        for (int j = tid; j < NN; j += 256) {
            float v = dist[j];
            if (v < best) { best = v; bi = j; }
        }
        rv[tid] = best; ri[tid] = bi;
        __syncthreads();
        for (int off = 128; off > 0; off >>= 1) {
            if (tid < off) {
                float v = rv[tid + off]; int b = ri[tid + off];
                if (v < rv[tid] || (v == rv[tid] && b < ri[tid])) { rv[tid] = v; ri[tid] = b; }
            }
            __syncthreads();
        }
        if (tid == 0) {
            int b = ri[0];
            idx_out[i * KK + kk] = b;
            ed_out[i * KK + kk] = sqrtf(fmaxf(rv[0], 1e-12f));
            dist[b] = 3.4e38f;
        }
        __syncthreads();
    }
}

// ---------------- gaussian RBF over 32 bins ----------------
__global__ void rbf_kernel(const float* __restrict__ ed, float* __restrict__ rbf) {
    int t = blockIdx.x * blockDim.x + threadIdx.x;
    if (t >= NN * KK * BB) return;
    int b = t & (BB - 1);
    int ik = t >> 5;
    float d = ed[ik];
    float c = 32.0f * (float)b * (1.0f / 31.0f);  // linspace(0, 32, 32)
    float x = d - c;                               // width = 1.0
    rbf[t] = expf(-x * x);
}

// ---------------- fused message: ew = rbf@W_rad, msg = h[idx]*ew, mean over K ----------------
__global__ __launch_bounds__(DD) void msg_kernel(const float* __restrict__ h,
                                                 const int* __restrict__ idx,
                                                 const float* __restrict__ rbf,
                                                 const float* __restrict__ Wrad,
                                                 float* __restrict__ out) {
    __shared__ float rs[KK * BB];        // 4 KB
    __shared__ float ws[BB * DD];        // 32 KB
    __shared__ int js[KK];
    int i = blockIdx.x;
    int tid = threadIdx.x;
    for (int x = tid; x < KK * BB; x += DD) rs[x] = rbf[i * (KK * BB) + x];
    for (int x = tid; x < BB * DD; x += DD) ws[x] = Wrad[x];
    if (tid < KK) js[tid] = idx[i * KK + tid];
    __syncthreads();
    float acc = 0.0f;
    int d = tid;
    #pragma unroll 4
    for (int k = 0; k < KK; k++) {
        const float* hrow = h + (size_t)js[k] * DD;
        float ew = 0.0f;
        #pragma unroll
        for (int b = 0; b < BB; b++) ew += rs[k * BB + b] * ws[b * DD + d];
        acc += hrow[d] * ew;
    }
    out[i * DD + d] = acc * (1.0f / KK);
}

// ---------------- tiled fp32 GEMM: C[M,Nc] = A[M,Kd] @ B[Kd,Nc] (+C if ACCUM) ----------------
#define BM 64
#define BN 64
#define BKT 16
template <bool ACCUM>
__global__ __launch_bounds__(256) void gemm_kernel(const float* __restrict__ A,
                                                   const float* __restrict__ Bm,
                                                   float* __restrict__ C,
                                                   int M, int Nc, int Kd, int ldc) {
    __shared__ float As[BKT][BM + 1];
    __shared__ float Bs[BKT][BN];
    int tid = threadIdx.x;
    int bm = blockIdx.y * BM, bn = blockIdx.x * BN;
    int ty = tid >> 4, tx = tid & 15;
    float acc[4][4] = {};
    for (int k0 = 0; k0 < Kd; k0 += BKT) {
        #pragma unroll
        for (int i = 0; i < 4; i++) {
            int li = tid + i * 256;
            int kk = li & 15, mm = li >> 4;
            int kg = k0 + kk;
            As[kk][mm] = (kg < Kd) ? A[(size_t)(bm + mm) * Kd + kg] : 0.0f;
        }
        #pragma unroll
        for (int i = 0; i < 4; i++) {
            int li = tid + i * 256;
            int nn = li & 63, kk = li >> 6;
            int kg = k0 + kk;
            Bs[kk][nn] = (kg < Kd) ? Bm[(size_t)kg * Nc + bn + nn] : 0.0f;
        }
        __syncthreads();
        #pragma unroll
        for (int kk = 0; kk < BKT; kk++) {
            float a[4], b[4];
            #pragma unroll
            for (int i = 0; i < 4; i++) a[i] = As[kk][ty * 4 + i];
            float4 b4 = *reinterpret_cast<const float4*>(&Bs[kk][tx * 4]);
            b[0] = b4.x; b[1] = b4.y; b[2] = b4.z; b[3] = b4.w;
            #pragma unroll
            for (int i = 0; i < 4; i++)
                #pragma unroll
                for (int j = 0; j < 4; j++) acc[i][j] += a[i] * b[j];
        }
        __syncthreads();
    }
    #pragma unroll
    for (int i = 0; i < 4; i++) {
        int m = bm + ty * 4 + i;
        #pragma unroll
        for (int j = 0; j < 4; j++) {
            int n = bn + tx * 4 + j;
            float v = acc[i][j];
            if (ACCUM) v += C[(size_t)m * ldc + n];
            C[(size_t)m * ldc + n] = v;
        }
    }
}

// ---------------- coord head: d_out[:,256:259] = out @ W_coord ----------------
__global__ void coord_out_kernel(const float* __restrict__ out,
                                 const float* __restrict__ Wc,
                                 float* __restrict__ dout) {
    int i = blockIdx.x;
    int w = threadIdx.x >> 5, lane = threadIdx.x & 31;
    float s = 0.0f;
    for (int d = lane; d < DD; d += 32) s += out[i * DD + d] * Wc[d * 3 + w];
    #pragma unroll
    for (int o = 16; o > 0; o >>= 1) s += __shfl_down_sync(0xFFFFFFFFu, s, o);
    if (lane == 0) dout[(size_t)i * (DD + 3) + DD + w] = s;
}

// ---------------- host launcher ----------------
static void* symaddr(const void* s) {
    void* p = nullptr;
    cudaGetSymbolAddress(&p, s);
    return p;
}

extern "C" void kernel_launch(void* const* d_in, const int* in_sizes, int n_in,
                              void* d_out, int out_size) {
    const float* feat   = (const float*)d_in[0];
    const float* coord  = (const float*)d_in[1];
    const float* mask   = (const float*)d_in[2];
    const float* tptr   = (const float*)d_in[3];
    const float* pos    = (const float*)d_in[4];
    const float* W_in   = (const float*)d_in[5];
    const float* W_self = (const float*)d_in[6];
    const float* W_rad  = (const float*)d_in[7];
    const float* W_conv = (const float*)d_in[8];
    const float* W_cat  = (const float*)d_in[9];
    const float* W_out  = (const float*)d_in[10];
    const float* W_noise= (const float*)d_in[11];
    const float* W_coord= (const float*)d_in[12];
    float* out = (float*)d_out;

    float* p_in     = (float*)symaddr(g_in);
    float* p_t0     = (float*)symaddr(g_t0);
    float* p_h      = (float*)symaddr(g_h);
    float* p_hs     = (float*)symaddr(g_hs);
    float* p_msg    = (float*)symaddr(g_msg);
    float* p_agg    = (float*)symaddr(g_agg);
    float* p_states = (float*)symaddr(g_states);
    float* p_out    = (float*)symaddr(g_out);
    int*   p_idx    = (int*)symaddr(g_idx);
    float* p_ed     = (float*)symaddr(g_ed);
    float* p_rbf    = (float*)symaddr(g_rbf);

    dim3 ggemm(DD / BN, NN / BM);   // (4, 64)

    // 1. build concat input
    build_in_kernel<<<NN, 128>>>(feat, pos, mask, tptr, p_in);
    // 2. h = layernorm(in @ W_in) * mask ; states[0] = h
    gemm_kernel<false><<<ggemm, 256>>>(p_in, W_in, p_t0, NN, DD, CIN, DD);
    ln_kernel<<<NN, DD>>>(p_t0, p_h, mask, p_states, 0);
    // 3. kNN + RBF
    knn_kernel<<<NN, 256>>>(coord, p_idx, p_ed);
    rbf_kernel<<<(NN * KK * BB + 255) / 256, 256>>>(p_ed, p_rbf);

    for (int l = 0; l < LL; l++) {
        const float* Wself_l = W_self + (size_t)l * DD * DD;
        const float* Wrad_l  = W_rad  + (size_t)l * BB * DD;
        const float* Wconv_l = W_conv + (size_t)l * DD * DD;
        const float* Wcat_t  = W_cat  + (size_t)l * 2 * DD * DD;          // rows 0..255 (res)
        const float* Wcat_b  = Wcat_t + (size_t)DD * DD;                  // rows 256..511 (agg)

        // hs = layernorm(h @ W_self[l])
        gemm_kernel<false><<<ggemm, 256>>>(p_h, Wself_l, p_t0, NN, DD, DD, DD);
        ln_kernel<<<NN, DD>>>(p_t0, p_hs, nullptr, nullptr, 0);
        // msg = mean_k( hs[idx] * (rbf @ W_rad[l]) )
        msg_kernel<<<NN, DD>>>(p_hs, p_idx, p_rbf, Wrad_l, p_msg);
        // agg = msg @ W_conv[l]
        gemm_kernel<false><<<ggemm, 256>>>(p_msg, Wconv_l, p_agg, NN, DD, DD, DD);
        // t0 = res @ Wcat_top + agg @ Wcat_bot
        gemm_kernel<false><<<ggemm, 256>>>(p_h, Wcat_t, p_t0, NN, DD, DD, DD);
        gemm_kernel<true><<<ggemm, 256>>>(p_agg, Wcat_b, p_t0, NN, DD, DD, DD);
        // h = layernorm(t0) * mask ; states[l+1] = h
        ln_kernel<<<NN, DD>>>(p_t0, p_h, mask, p_states, l + 1);
    }

    // out = states @ W_out  ([4096,1280] @ [1280,256])
    gemm_kernel<false><<<ggemm, 256>>>(p_states, W_out, p_out, NN, DD, NSTATE * DD, DD);
    // d_out[:, :256] = out @ W_noise  (ldc = 259)
    gemm_kernel<false><<<ggemm, 256>>>(p_out, W_noise, out, NN, DD, DD, DD + 3);
    // d_out[:, 256:259] = out @ W_coord
    coord_out_kernel<<<NN, 96>>>(p_out, W_coord, out);
}

// round 3
// speedup vs baseline: 1.2294x; 1.2294x over previous
#include <cuda_runtime.h>
#include <cuda_bf16.h>
#include <math.h>

#define NN 4096
#define DD 256
#define KK 32
#define LL 4
#define TT 100
#define PP 64
#define BB 32
#define CIN 420   // T + D + P
#define NSTATE 5  // L+1

// ---------------- scratch (device globals; no allocations) ----------------
__device__ float g_in[NN * CIN];
__device__ float g_t0[NN * DD];          // gemm output before LN
__device__ float g_h[NN * DD];           // current h (post-LN, masked)
__device__ float g_hs[NN * DD];          // layernorm(h @ W_self)
__device__ float g_msg[NN * DD];         // mean message
__device__ float g_agg[NN * DD];         // msg @ W_conv
__device__ float g_states[NN * NSTATE * DD];
__device__ float g_out[NN * DD];         // states @ W_out
__device__ int   g_idx[NN * KK];
__device__ float g_ed[NN * KK];
__device__ float g_rbf[NN * KK * BB];

// ---------------- input build: concat(time_embed*mask, feat, pos) ----------------
__global__ void build_in_kernel(const float* __restrict__ feat,
                                const float* __restrict__ pos,
                                const float* __restrict__ mask,
                                const float* __restrict__ tptr,
                                float* __restrict__ out) {
    int i = blockIdx.x;
    float t = *tptr;
    float mk = mask[i];
    for (int c = threadIdx.x; c < CIN; c += blockDim.x) {
        float v;
        if (c < TT) {
            float d = (t - (float)c * (1.0f / 99.0f)) * 99.0f;
            float a = fabsf(d);
            if (a < 1.0f) {
                float cc = cospif(0.5f * d);
                v = cc * cc * mk;
            } else {
                v = 0.0f;
            }
        } else if (c < TT + DD) {
            v = feat[i * DD + (c - TT)];
        } else {
            v = pos[i * PP + (c - TT - DD)];
        }
        out[i * CIN + c] = v;
    }
}

// ---------------- layernorm over D=256, one block per row ----------------
__global__ __launch_bounds__(DD) void ln_kernel(const float* __restrict__ X,
                                                float* __restrict__ Y,
                                                const float* __restrict__ mask,
                                                float* __restrict__ states,
                                                int state_col) {
    int i = blockIdx.x;
    int tid = threadIdx.x;
    float x = X[i * DD + tid];
    __shared__ float red[8];
    float s = x;
    #pragma unroll
    for (int o = 16; o > 0; o >>= 1) s += __shfl_down_sync(0xFFFFFFFFu, s, o);
    if ((tid & 31) == 0) red[tid >> 5] = s;
    __syncthreads();
    float tot = 0.0f;
    if (tid < 8) tot = red[tid];
    #pragma unroll
    for (int o = 4; o > 0; o >>= 1) tot += __shfl_down_sync(0xFFu, tot, o);
    __shared__ float mean_s, var_s;
    if (tid == 0) mean_s = tot * (1.0f / DD);
    __syncthreads();
    float m = mean_s;
    float dv = x - m;
    float s2 = dv * dv;
    #pragma unroll
    for (int o = 16; o > 0; o >>= 1) s2 += __shfl_down_sync(0xFFFFFFFFu, s2, o);
    if ((tid & 31) == 0) red[tid >> 5] = s2;
    __syncthreads();
    float tot2 = 0.0f;
    if (tid < 8) tot2 = red[tid];
    #pragma unroll
    for (int o = 4; o > 0; o >>= 1) tot2 += __shfl_down_sync(0xFFu, tot2, o);
    if (tid == 0) var_s = tot2 * (1.0f / DD);
    __syncthreads();
    float y = dv * rsqrtf(var_s + 1e-5f);
    if (mask) y *= mask[i];
    Y[i * DD + tid] = y;
    if (states) states[(size_t)i * (NSTATE * DD) + state_col * DD + tid] = y;
}

// ---------------- kNN: block per row, cached per-thread argmin + warp-shuffle reduce ----------------
__global__ __launch_bounds__(256) void knn_kernel(const float* __restrict__ coord,
                                                  int* __restrict__ idx_out,
                                                  float* __restrict__ ed_out) {
    __shared__ float dist[NN];
    __shared__ float wv[8];
    __shared__ int wi[8];
    __shared__ int s_sel;
    int i = blockIdx.x;
    int tid = threadIdx.x;
    int lane = tid & 31;
    int warp = tid >> 5;
    float cx = coord[i * 3 + 0];
    float cy = coord[i * 3 + 1];
    float cz = coord[i * 3 + 2];
    // compute dists; track per-thread local (min, idx) in increasing-j order (strict <)
    float v = 3.4e38f;
    int bi = 0x7FFFFFFF;
    for (int j = tid; j < NN; j += 256) {
        float dx = cx - coord[j * 3 + 0];
        float dy = cy - coord[j * 3 + 1];
        float dz = cz - coord[j * 3 + 2];
        float d2 = dx * dx + dy * dy + dz * dz;
        if (j == i) d2 += 1e9f;
        dist[j] = d2;
        if (d2 < v) { v = d2; bi = j; }
    }
    __syncthreads();
    for (int kk = 0; kk < KK; kk++) {
        // warp reduce (val, idx) with smallest-idx tie-break
        float rv = v; int rb = bi;
        #pragma unroll
        for (int o = 16; o > 0; o >>= 1) {
            float ov = __shfl_down_sync(0xFFFFFFFFu, rv, o);
            int ob = __shfl_down_sync(0xFFFFFFFFu, rb, o);
            if (ov < rv || (ov == rv && ob < rb)) { rv = ov; rb = ob; }
        }
        if (lane == 0) { wv[warp] = rv; wi[warp] = rb; }
        __syncthreads();
        if (warp == 0) {
            float v2 = (lane < 8) ? wv[lane] : 3.4e38f;
            int b2 = (lane < 8) ? wi[lane] : 0x7FFFFFFF;
            #pragma unroll
            for (int o = 4; o > 0; o >>= 1) {
                float ov = __shfl_down_sync(0xFFFFFFFFu, v2, o);
                int ob = __shfl_down_sync(0xFFFFFFFFu, b2, o);
                if (ov < v2 || (ov == v2 && ob < b2)) { v2 = ov; b2 = ob; }
            }
            if (lane == 0) {
                idx_out[i * KK + kk] = b2;
                ed_out[i * KK + kk] = sqrtf(fmaxf(v2, 1e-12f));
                dist[b2] = 3.4e38f;
                s_sel = b2;
            }
        }
        __syncthreads();
        // only the owning thread rescans its strided slice
        int b = s_sel;
        if ((b & 255) == tid) {
            v = 3.4e38f; bi = 0x7FFFFFFF;
            for (int j = tid; j < NN; j += 256) {
                float d2 = dist[j];
                if (d2 < v) { v = d2; bi = j; }
            }
        }
    }
}

// ---------------- gaussian RBF over 32 bins ----------------
__global__ void rbf_kernel(const float* __restrict__ ed, float* __restrict__ rbf) {
    int t = blockIdx.x * blockDim.x + threadIdx.x;
    if (t >= NN * KK * BB) return;
    int b = t & (BB - 1);
    int ik = t >> 5;
    float d = ed[ik];
    float c = 32.0f * (float)b * (1.0f / 31.0f);
    float x = d - c;
    rbf[t] = expf(-x * x);
}

// ---------------- fused message: ew = rbf@W_rad, msg = h[idx]*ew, mean over K ----------------
__global__ __launch_bounds__(DD) void msg_kernel(const float* __restrict__ h,
                                                 const int* __restrict__ idx,
                                                 const float* __restrict__ rbf,
                                                 const float* __restrict__ Wrad,
                                                 float* __restrict__ out) {
    __shared__ float rs[KK * BB];
    __shared__ float ws[BB * DD];
    __shared__ int js[KK];
    int i = blockIdx.x;
    int tid = threadIdx.x;
    for (int x = tid; x < KK * BB; x += DD) rs[x] = rbf[i * (KK * BB) + x];
    for (int x = tid; x < BB * DD; x += DD) ws[x] = Wrad[x];
    if (tid < KK) js[tid] = idx[i * KK + tid];
    __syncthreads();
    float acc = 0.0f;
    int d = tid;
    #pragma unroll 4
    for (int k = 0; k < KK; k++) {
        const float* hrow = h + (size_t)js[k] * DD;
        float ew = 0.0f;
        #pragma unroll
        for (int b = 0; b < BB; b++) ew += rs[k * BB + b] * ws[b * DD + d];
        acc += hrow[d] * ew;
    }
    out[i * DD + d] = acc * (1.0f / KK);
}

// ---------------- tiled fp32 GEMM, vectorized + reg double-buffered ----------------
// C[M,Nc] = A[M,Kd] @ B[Kd,Nc] (+= if ACCUM). 64x64 tile, BK=16, 256 threads, 4x4 micro.
#define BM 64
#define BN 64
#define BKT 16
#define AP 68   // padded As row (floats), 16B-aligned stride
template <bool ACCUM>
__global__ __launch_bounds__(256) void gemm_kernel(const float* __restrict__ A,
                                                   const float* __restrict__ Bm,
                                                   float* __restrict__ C,
                                                   int M, int Nc, int Kd, int ldc) {
    __shared__ float As[BKT * AP];   // As[k * AP + m]
    __shared__ float Bs[BKT * BN];   // Bs[k * BN + n]
    int tid = threadIdx.x;
    int bm = blockIdx.y * BM, bn = blockIdx.x * BN;
    int ty = tid >> 4, tx = tid & 15;

    int mm = tid >> 2;
    int kk4 = (tid & 3) * 4;
    int rb = tid >> 4;
    int cb = (tid & 15) * 4;

    const float* Arow = A + (size_t)(bm + mm) * Kd;
    const float* Brow = Bm + (size_t)rb * Nc + bn + cb;

    float4 av, bv;
    // prologue: load tile 0 into regs
    {
        if (BKT <= Kd) {
            av = *reinterpret_cast<const float4*>(Arow + kk4);
            bv = *reinterpret_cast<const float4*>(Brow);
        } else {
            av = make_float4(0.f, 0.f, 0.f, 0.f);
            bv = make_float4(0.f, 0.f, 0.f, 0.f);
        }
    }
    As[(kk4 + 0) * AP + mm] = av.x;
    As[(kk4 + 1) * AP + mm] = av.y;
    As[(kk4 + 2) * AP + mm] = av.z;
    As[(kk4 + 3) * AP + mm] = av.w;
    *reinterpret_cast<float4*>(&Bs[rb * BN + cb]) = bv;
    __syncthreads();

    float acc[4][4] = {};
    for (int k0 = 0;;) {
        int knext = k0 + BKT;
        bool has_next = knext < Kd;
        if (has_next) {
            if (knext + BKT <= Kd) {
                av = *reinterpret_cast<const float4*>(Arow + knext + kk4);
                bv = *reinterpret_cast<const float4*>(Brow + (size_t)knext * Nc);
            } else {
                float a0 = (knext + kk4 + 0 < Kd) ? Arow[knext + kk4 + 0] : 0.0f;
                float a1 = (knext + kk4 + 1 < Kd) ? Arow[knext + kk4 + 1] : 0.0f;
                float a2 = (knext + kk4 + 2 < Kd) ? Arow[knext + kk4 + 2] : 0.0f;
                float a3 = (knext + kk4 + 3 < Kd) ? Arow[knext + kk4 + 3] : 0.0f;
                av = make_float4(a0, a1, a2, a3);
                if (knext + rb < Kd) bv = *reinterpret_cast<const float4*>(Brow + (size_t)knext * Nc);
                else bv = make_float4(0.f, 0.f, 0.f, 0.f);
            }
        }
        #pragma unroll
        for (int kk = 0; kk < BKT; kk++) {
            float4 a4 = *reinterpret_cast<const float4*>(&As[kk * AP + ty * 4]);
            float4 b4 = *reinterpret_cast<const float4*>(&Bs[kk * BN + tx * 4]);
            float a[4] = {a4.x, a4.y, a4.z, a4.w};
            float b[4] = {b4.x, b4.y, b4.z, b4.w};
            #pragma unroll
            for (int ii = 0; ii < 4; ii++)
                #pragma unroll
                for (int jj = 0; jj < 4; jj++) acc[ii][jj] += a[ii] * b[jj];
        }
        if (!has_next) break;
        __syncthreads();
        As[(kk4 + 0) * AP + mm] = av.x;
        As[(kk4 + 1) * AP + mm] = av.y;
        As[(kk4 + 2) * AP + mm] = av.z;
        As[(kk4 + 3) * AP + mm] = av.w;
        *reinterpret_cast<float4*>(&Bs[rb * BN + cb]) = bv;
        __syncthreads();
        k0 = knext;
    }

    // epilogue: float4 only when every C row base is 16B-aligned (ldc % 4 == 0)
    if ((ldc & 3) == 0) {
        #pragma unroll
        for (int ii = 0; ii < 4; ii++) {
            int m = bm + ty * 4 + ii;
            int n = bn + tx * 4;
            float* crow = C + (size_t)m * ldc + n;
            float4 v = make_float4(acc[ii][0], acc[ii][1], acc[ii][2], acc[ii][3]);
            if (ACCUM) {
                float4 c0 = *reinterpret_cast<const float4*>(crow);
                v.x += c0.x; v.y += c0.y; v.z += c0.z; v.w += c0.w;
            }
            *reinterpret_cast<float4*>(crow) = v;
        }
    } else {
        #pragma unroll
        for (int ii = 0; ii < 4; ii++) {
            int m = bm + ty * 4 + ii;
            int n = bn + tx * 4;
            float* crow = C + (size_t)m * ldc + n;
            #pragma unroll
            for (int jj = 0; jj < 4; jj++) {
                float v = acc[ii][jj];
                if (ACCUM) v += crow[jj];
                crow[jj] = v;
            }
        }
    }
}

// ---------------- coord head: d_out[:,256:259] = out @ W_coord ----------------
__global__ void coord_out_kernel(const float* __restrict__ out,
                                 const float* __restrict__ Wc,
                                 float* __restrict__ dout) {
    int i = blockIdx.x;
    int w = threadIdx.x >> 5, lane = threadIdx.x & 31;
    float s = 0.0f;
    for (int d = lane; d < DD; d += 32) s += out[i * DD + d] * Wc[d * 3 + w];
    #pragma unroll
    for (int o = 16; o > 0; o >>= 1) s += __shfl_down_sync(0xFFFFFFFFu, s, o);
    if (lane == 0) dout[(size_t)i * (DD + 3) + DD + w] = s;
}

// ---------------- host launcher ----------------
static void* symaddr(const void* s) {
    void* p = nullptr;
    cudaGetSymbolAddress(&p, s);
    return p;
}

extern "C" void kernel_launch(void* const* d_in, const int* in_sizes, int n_in,
                              void* d_out, int out_size) {
    const float* feat   = (const float*)d_in[0];
    const float* coord  = (const float*)d_in[1];
    const float* mask   = (const float*)d_in[2];
    const float* tptr   = (const float*)d_in[3];
    const float* pos    = (const float*)d_in[4];
    const float* W_in   = (const float*)d_in[5];
    const float* W_self = (const float*)d_in[6];
    const float* W_rad  = (const float*)d_in[7];
    const float* W_conv = (const float*)d_in[8];
    const float* W_cat  = (const float*)d_in[9];
    const float* W_out  = (const float*)d_in[10];
    const float* W_noise= (const float*)d_in[11];
    const float* W_coord= (const float*)d_in[12];
    float* out = (float*)d_out;

    float* p_in     = (float*)symaddr(g_in);
    float* p_t0     = (float*)symaddr(g_t0);
    float* p_h      = (float*)symaddr(g_h);
    float* p_hs     = (float*)symaddr(g_hs);
    float* p_msg    = (float*)symaddr(g_msg);
    float* p_agg    = (float*)symaddr(g_agg);
    float* p_states = (float*)symaddr(g_states);
    float* p_out    = (float*)symaddr(g_out);
    int*   p_idx    = (int*)symaddr(g_idx);
    float* p_ed     = (float*)symaddr(g_ed);
    float* p_rbf    = (float*)symaddr(g_rbf);

    dim3 ggemm(DD / BN, NN / BM);   // (4, 64)

    // 1. build concat input
    build_in_kernel<<<NN, 128>>>(feat, pos, mask, tptr, p_in);
    // 2. h = layernorm(in @ W_in) * mask ; states[0] = h
    gemm_kernel<false><<<ggemm, 256>>>(p_in, W_in, p_t0, NN, DD, CIN, DD);
    ln_kernel<<<NN, DD>>>(p_t0, p_h, mask, p_states, 0);
    // 3. kNN + RBF
    knn_kernel<<<NN, 256>>>(coord, p_idx, p_ed);
    rbf_kernel<<<(NN * KK * BB + 255) / 256, 256>>>(p_ed, p_rbf);

    for (int l = 0; l < LL; l++) {
        const float* Wself_l = W_self + (size_t)l * DD * DD;
        const float* Wrad_l  = W_rad  + (size_t)l * BB * DD;
        const float* Wconv_l = W_conv + (size_t)l * DD * DD;
        const float* Wcat_t  = W_cat  + (size_t)l * 2 * DD * DD;
        const float* Wcat_b  = Wcat_t + (size_t)DD * DD;

        gemm_kernel<false><<<ggemm, 256>>>(p_h, Wself_l, p_t0, NN, DD, DD, DD);
        ln_kernel<<<NN, DD>>>(p_t0, p_hs, nullptr, nullptr, 0);
        msg_kernel<<<NN, DD>>>(p_hs, p_idx, p_rbf, Wrad_l, p_msg);
        gemm_kernel<false><<<ggemm, 256>>>(p_msg, Wconv_l, p_agg, NN, DD, DD, DD);
        gemm_kernel<false><<<ggemm, 256>>>(p_h, Wcat_t, p_t0, NN, DD, DD, DD);
        gemm_kernel<true><<<ggemm, 256>>>(p_agg, Wcat_b, p_t0, NN, DD, DD, DD);
        ln_kernel<<<NN, DD>>>(p_t0, p_h, mask, p_states, l + 1);
    }

    gemm_kernel<false><<<ggemm, 256>>>(p_states, W_out, p_out, NN, DD, NSTATE * DD, DD);
    gemm_kernel<false><<<ggemm, 256>>>(p_out, W_noise, out, NN, DD, DD, DD + 3);
    coord_out_kernel<<<NN, 96>>>(p_out, W_coord, out);
}

// round 4
// speedup vs baseline: 1.5693x; 1.2764x over previous
#include <cuda_runtime.h>
#include <cuda_bf16.h>
#include <math.h>

#define NN 4096
#define DD 256
#define KK 32
#define LL 4
#define TT 100
#define PP 64
#define BB 32
#define CIN 420   // T + D + P
#define NSTATE 5  // L+1

// ---------------- scratch (device globals; no allocations) ----------------
__device__ float g_in[NN * CIN];
__device__ float g_t0[NN * DD];          // gemm output before LN
__device__ float g_cat[NN * 2 * DD];     // [h | agg] fused concat buffer (ld 512)
__device__ float g_hs[NN * DD];          // layernorm(h @ W_self)
__device__ float g_msg[NN * DD];         // mean message
__device__ float g_states[NN * NSTATE * DD];
__device__ float g_out[NN * DD];         // states @ W_out
__device__ int   g_idx[NN * KK];
__device__ float g_ed[NN * KK];
__device__ float g_rbf[NN * KK * BB];

// ---------------- input build: concat(time_embed*mask, feat, pos) ----------------
__global__ void build_in_kernel(const float* __restrict__ feat,
                                const float* __restrict__ pos,
                                const float* __restrict__ mask,
                                const float* __restrict__ tptr,
                                float* __restrict__ out) {
    int i = blockIdx.x;
    float t = *tptr;
    float mk = mask[i];
    for (int c = threadIdx.x; c < CIN; c += blockDim.x) {
        float v;
        if (c < TT) {
            float d = (t - (float)c * (1.0f / 99.0f)) * 99.0f;
            float a = fabsf(d);
            if (a < 1.0f) {
                float cc = cospif(0.5f * d);
                v = cc * cc * mk;
            } else {
                v = 0.0f;
            }
        } else if (c < TT + DD) {
            v = feat[i * DD + (c - TT)];
        } else {
            v = pos[i * PP + (c - TT - DD)];
        }
        out[i * CIN + c] = v;
    }
}

// ---------------- layernorm over D=256, one block per row ----------------
__global__ __launch_bounds__(DD) void ln_kernel(const float* __restrict__ X,
                                                float* __restrict__ Y, int ldy,
                                                const float* __restrict__ mask,
                                                float* __restrict__ states,
                                                int state_col) {
    int i = blockIdx.x;
    int tid = threadIdx.x;
    float x = X[i * DD + tid];
    __shared__ float red[8];
    float s = x;
    #pragma unroll
    for (int o = 16; o > 0; o >>= 1) s += __shfl_down_sync(0xFFFFFFFFu, s, o);
    if ((tid & 31) == 0) red[tid >> 5] = s;
    __syncthreads();
    float tot = 0.0f;
    if (tid < 8) tot = red[tid];
    #pragma unroll
    for (int o = 4; o > 0; o >>= 1) tot += __shfl_down_sync(0xFFu, tot, o);
    __shared__ float mean_s, var_s;
    if (tid == 0) mean_s = tot * (1.0f / DD);
    __syncthreads();
    float m = mean_s;
    float dv = x - m;
    float s2 = dv * dv;
    #pragma unroll
    for (int o = 16; o > 0; o >>= 1) s2 += __shfl_down_sync(0xFFFFFFFFu, s2, o);
    if ((tid & 31) == 0) red[tid >> 5] = s2;
    __syncthreads();
    float tot2 = 0.0f;
    if (tid < 8) tot2 = red[tid];
    #pragma unroll
    for (int o = 4; o > 0; o >>= 1) tot2 += __shfl_down_sync(0xFFu, tot2, o);
    if (tid == 0) var_s = tot2 * (1.0f / DD);
    __syncthreads();
    float y = dv * rsqrtf(var_s + 1e-5f);
    if (mask) y *= mask[i];
    Y[(size_t)i * ldy + tid] = y;
    if (states) states[(size_t)i * (NSTATE * DD) + state_col * DD + tid] = y;
}

// ---------------- kNN: block per row, cached per-thread argmin + warp-shuffle reduce ----------------
__global__ __launch_bounds__(256) void knn_kernel(const float* __restrict__ coord,
                                                  int* __restrict__ idx_out,
                                                  float* __restrict__ ed_out) {
    __shared__ float dist[NN];
    __shared__ float wv[8];
    __shared__ int wi[8];
    __shared__ int s_sel;
    int i = blockIdx.x;
    int tid = threadIdx.x;
    int lane = tid & 31;
    int warp = tid >> 5;
    float cx = coord[i * 3 + 0];
    float cy = coord[i * 3 + 1];
    float cz = coord[i * 3 + 2];
    float v = 3.4e38f;
    int bi = 0x7FFFFFFF;
    for (int j = tid; j < NN; j += 256) {
        float dx = cx - coord[j * 3 + 0];
        float dy = cy - coord[j * 3 + 1];
        float dz = cz - coord[j * 3 + 2];
        float d2 = dx * dx + dy * dy + dz * dz;
        if (j == i) d2 += 1e9f;
        dist[j] = d2;
        if (d2 < v) { v = d2; bi = j; }
    }
    __syncthreads();
    for (int kk = 0; kk < KK; kk++) {
        float rv = v; int rb = bi;
        #pragma unroll
        for (int o = 16; o > 0; o >>= 1) {
            float ov = __shfl_down_sync(0xFFFFFFFFu, rv, o);
            int ob = __shfl_down_sync(0xFFFFFFFFu, rb, o);
            if (ov < rv || (ov == rv && ob < rb)) { rv = ov; rb = ob; }
        }
        if (lane == 0) { wv[warp] = rv; wi[warp] = rb; }
        __syncthreads();
        if (warp == 0) {
            float v2 = (lane < 8) ? wv[lane] : 3.4e38f;
            int b2 = (lane < 8) ? wi[lane] : 0x7FFFFFFF;
            #pragma unroll
            for (int o = 4; o > 0; o >>= 1) {
                float ov = __shfl_down_sync(0xFFFFFFFFu, v2, o);
                int ob = __shfl_down_sync(0xFFFFFFFFu, b2, o);
                if (ov < v2 || (ov == v2 && ob < b2)) { v2 = ov; b2 = ob; }
            }
            if (lane == 0) {
                idx_out[i * KK + kk] = b2;
                ed_out[i * KK + kk] = sqrtf(fmaxf(v2, 1e-12f));
                dist[b2] = 3.4e38f;
                s_sel = b2;
            }
        }
        __syncthreads();
        int b = s_sel;
        if ((b & 255) == tid) {
            v = 3.4e38f; bi = 0x7FFFFFFF;
            for (int j = tid; j < NN; j += 256) {
                float d2 = dist[j];
                if (d2 < v) { v = d2; bi = j; }
            }
        }
    }
}

// ---------------- gaussian RBF over 32 bins ----------------
__global__ void rbf_kernel(const float* __restrict__ ed, float* __restrict__ rbf) {
    int t = blockIdx.x * blockDim.x + threadIdx.x;
    if (t >= NN * KK * BB) return;
    int b = t & (BB - 1);
    int ik = t >> 5;
    float d = ed[ik];
    float c = 32.0f * (float)b * (1.0f / 31.0f);
    float x = d - c;
    rbf[t] = expf(-x * x);
}

// ---------------- fused message: ew = rbf@W_rad, msg = h[idx]*ew, mean over K ----------------
__global__ __launch_bounds__(DD) void msg_kernel(const float* __restrict__ h,
                                                 const int* __restrict__ idx,
                                                 const float* __restrict__ rbf,
                                                 const float* __restrict__ Wrad,
                                                 float* __restrict__ out) {
    __shared__ float rs[KK * BB];
    __shared__ float ws[BB * DD];
    __shared__ int js[KK];
    int i = blockIdx.x;
    int tid = threadIdx.x;
    for (int x = tid; x < KK * BB; x += DD) rs[x] = rbf[i * (KK * BB) + x];
    for (int x = tid; x < BB * DD; x += DD) ws[x] = Wrad[x];
    if (tid < KK) js[tid] = idx[i * KK + tid];
    __syncthreads();
    float acc = 0.0f;
    int d = tid;
    #pragma unroll 4
    for (int k = 0; k < KK; k++) {
        const float* hrow = h + (size_t)js[k] * DD;
        float ew = 0.0f;
        #pragma unroll
        for (int b = 0; b < BB; b++) ew += rs[k * BB + b] * ws[b * DD + d];
        acc += hrow[d] * ew;
    }
    out[i * DD + d] = acc * (1.0f / KK);
}

// ================= tf32 tensor-core GEMM =================
// C[M,Nc] = A[M,Kd](lda) @ B[Kd,Nc]  via mma.m16n8k8 tf32.
// 128x64 block tile, BK=32, 256 threads / 8 warps, warp tile 32x32.
#define GBM 128
#define GBN 64
#define GBK 32
#define ASTRIDE 36   // As[row][k], banks (gid*4+tig) distinct for frag loads
#define BSTRIDE 72   // Bs[k][n],  banks (tig*8+gid) distinct for frag loads

__device__ __forceinline__ float f2tf(float x) {
    unsigned r;
    asm("cvt.rna.tf32.f32 %0, %1;" : "=r"(r) : "f"(x));
    return __uint_as_float(r);
}

__device__ __forceinline__ void mma_tf32(float& d0, float& d1, float& d2, float& d3,
                                         unsigned a0, unsigned a1, unsigned a2, unsigned a3,
                                         unsigned b0, unsigned b1) {
    asm volatile(
        "mma.sync.aligned.m16n8k8.row.col.f32.tf32.tf32.f32 "
        "{%0,%1,%2,%3}, {%4,%5,%6,%7}, {%8,%9}, {%0,%1,%2,%3};"
        : "+f"(d0), "+f"(d1), "+f"(d2), "+f"(d3)
        : "r"(a0), "r"(a1), "r"(a2), "r"(a3), "r"(b0), "r"(b1));
}

__global__ __launch_bounds__(256) void mma_gemm_kernel(const float* __restrict__ A,
                                                       const float* __restrict__ Bm,
                                                       float* __restrict__ C,
                                                       int M, int Nc, int Kd,
                                                       int lda, int ldc) {
    __shared__ float As[GBM * ASTRIDE];   // [row][k]
    __shared__ float Bs[GBK * BSTRIDE];   // [k][n]
    int tid = threadIdx.x;
    int bm = blockIdx.y * GBM, bn = blockIdx.x * GBN;
    int warp = tid >> 5, lane = tid & 31;
    int warp_m = warp >> 1, warp_n = warp & 1;
    int gid = lane >> 2, tig = lane & 3;

    // loader mappings
    int arow = tid >> 3;            // 0..31 per it-step? no: idx>>3 below
    int ac4 = (tid & 7) * 4;
    int brow = tid >> 4;            // 0..15 base
    int bc4 = (tid & 15) * 4;
    (void)arow;

    const float* Abase = A + (size_t)bm * lda;
    const float* Bbase = Bm + bn;

    float4 avr[4];  // A prefetch: 4 float4 per thread (128x32 tile)
    float4 bvr[2];  // B prefetch: 2 float4 per thread (32x64 tile)

    // ---- load tile k0 into regs ----
    auto load_tile = [&](int k0) {
        #pragma unroll
        for (int it = 0; it < 4; it++) {
            int idx = it * 256 + tid;
            int r = idx >> 3;             // 0..127
            int c4 = (idx & 7) * 4;       // 0..28
            const float* p = Abase + (size_t)r * lda + k0 + c4;
            if (k0 + c4 + 4 <= Kd) {
                avr[it] = *reinterpret_cast<const float4*>(p);
            } else {
                float x0 = (k0 + c4 + 0 < Kd) ? p[0] : 0.0f;
                float x1 = (k0 + c4 + 1 < Kd) ? p[1] : 0.0f;
                float x2 = (k0 + c4 + 2 < Kd) ? p[2] : 0.0f;
                float x3 = (k0 + c4 + 3 < Kd) ? p[3] : 0.0f;
                avr[it] = make_float4(x0, x1, x2, x3);
            }
        }
        #pragma unroll
        for (int it = 0; it < 2; it++) {
            int idx = it * 256 + tid;
            int r = idx >> 4;             // 0..31 (k within tile)
            int c4 = (idx & 15) * 4;      // 0..60
            if (k0 + r < Kd) {
                bvr[it] = *reinterpret_cast<const float4*>(Bbase + (size_t)(k0 + r) * Nc + c4);
            } else {
                bvr[it] = make_float4(0.f, 0.f, 0.f, 0.f);
            }
        }
    };
    auto store_tile = [&]() {
        #pragma unroll
        for (int it = 0; it < 4; it++) {
            int idx = it * 256 + tid;
            int r = idx >> 3;
            int c4 = (idx & 7) * 4;
            float4 v = avr[it];
            *reinterpret_cast<float4*>(&As[r * ASTRIDE + c4]) =
                make_float4(f2tf(v.x), f2tf(v.y), f2tf(v.z), f2tf(v.w));
        }
        #pragma unroll
        for (int it = 0; it < 2; it++) {
            int idx = it * 256 + tid;
            int r = idx >> 4;
            int c4 = (idx & 15) * 4;
            float4 v = bvr[it];
            *reinterpret_cast<float4*>(&Bs[r * BSTRIDE + c4]) =
                make_float4(f2tf(v.x), f2tf(v.y), f2tf(v.z), f2tf(v.w));
        }
    };

    float cf[2][4][4];
    #pragma unroll
    for (int mt = 0; mt < 2; mt++)
        #pragma unroll
        for (int nt = 0; nt < 4; nt++)
            #pragma unroll
            for (int q = 0; q < 4; q++) cf[mt][nt][q] = 0.0f;

    load_tile(0);
    store_tile();
    __syncthreads();

    int r0a = warp_m * 32 + gid;            // A frag row (mt*16 added per mt)
    int ncol0 = warp_n * 32 + gid;          // B frag col base (nt*8 added per nt)

    for (int k0 = 0;;) {
        int knext = k0 + GBK;
        bool has_next = knext < Kd;
        if (has_next) load_tile(knext);
        #pragma unroll
        for (int ks = 0; ks < 4; ks++) {
            int kc = ks * 8 + tig;
            unsigned af[2][4];
            #pragma unroll
            for (int mt = 0; mt < 2; mt++) {
                int rb = (r0a + mt * 16) * ASTRIDE;
                af[mt][0] = __float_as_uint(As[rb + kc]);
                af[mt][1] = __float_as_uint(As[rb + 8 * ASTRIDE + kc]);
                af[mt][2] = __float_as_uint(As[rb + kc + 4]);
                af[mt][3] = __float_as_uint(As[rb + 8 * ASTRIDE + kc + 4]);
            }
            unsigned bf[4][2];
            #pragma unroll
            for (int nt = 0; nt < 4; nt++) {
                int cb = ncol0 + nt * 8;
                bf[nt][0] = __float_as_uint(Bs[(ks * 8 + tig) * BSTRIDE + cb]);
                bf[nt][1] = __float_as_uint(Bs[(ks * 8 + tig + 4) * BSTRIDE + cb]);
            }
            #pragma unroll
            for (int mt = 0; mt < 2; mt++)
                #pragma unroll
                for (int nt = 0; nt < 4; nt++)
                    mma_tf32(cf[mt][nt][0], cf[mt][nt][1], cf[mt][nt][2], cf[mt][nt][3],
                             af[mt][0], af[mt][1], af[mt][2], af[mt][3],
                             bf[nt][0], bf[nt][1]);
        }
        if (!has_next) break;
        __syncthreads();
        store_tile();
        __syncthreads();
        k0 = knext;
    }

    // epilogue
    int row_base = bm + warp_m * 32;
    int col_base = bn + warp_n * 32;
    if ((ldc & 1) == 0) {
        #pragma unroll
        for (int mt = 0; mt < 2; mt++) {
            #pragma unroll
            for (int nt = 0; nt < 4; nt++) {
                int r0 = row_base + mt * 16 + gid;
                int c = col_base + nt * 8 + tig * 2;
                *reinterpret_cast<float2*>(C + (size_t)r0 * ldc + c) =
                    make_float2(cf[mt][nt][0], cf[mt][nt][1]);
                *reinterpret_cast<float2*>(C + (size_t)(r0 + 8) * ldc + c) =
                    make_float2(cf[mt][nt][2], cf[mt][nt][3]);
            }
        }
    } else {
        #pragma unroll
        for (int mt = 0; mt < 2; mt++) {
            #pragma unroll
            for (int nt = 0; nt < 4; nt++) {
                int r0 = row_base + mt * 16 + gid;
                int c = col_base + nt * 8 + tig * 2;
                C[(size_t)r0 * ldc + c]           = cf[mt][nt][0];
                C[(size_t)r0 * ldc + c + 1]       = cf[mt][nt][1];
                C[(size_t)(r0 + 8) * ldc + c]     = cf[mt][nt][2];
                C[(size_t)(r0 + 8) * ldc + c + 1] = cf[mt][nt][3];
            }
        }
    }
}

// ---------------- coord head: d_out[:,256:259] = out @ W_coord ----------------
__global__ void coord_out_kernel(const float* __restrict__ out,
                                 const float* __restrict__ Wc,
                                 float* __restrict__ dout) {
    int i = blockIdx.x;
    int w = threadIdx.x >> 5, lane = threadIdx.x & 31;
    float s = 0.0f;
    for (int d = lane; d < DD; d += 32) s += out[i * DD + d] * Wc[d * 3 + w];
    #pragma unroll
    for (int o = 16; o > 0; o >>= 1) s += __shfl_down_sync(0xFFFFFFFFu, s, o);
    if (lane == 0) dout[(size_t)i * (DD + 3) + DD + w] = s;
}

// ---------------- host launcher ----------------
static void* symaddr(const void* s) {
    void* p = nullptr;
    cudaGetSymbolAddress(&p, s);
    return p;
}

extern "C" void kernel_launch(void* const* d_in, const int* in_sizes, int n_in,
                              void* d_out, int out_size) {
    const float* feat   = (const float*)d_in[0];
    const float* coord  = (const float*)d_in[1];
    const float* mask   = (const float*)d_in[2];
    const float* tptr   = (const float*)d_in[3];
    const float* pos    = (const float*)d_in[4];
    const float* W_in   = (const float*)d_in[5];
    const float* W_self = (const float*)d_in[6];
    const float* W_rad  = (const float*)d_in[7];
    const float* W_conv = (const float*)d_in[8];
    const float* W_cat  = (const float*)d_in[9];
    const float* W_out  = (const float*)d_in[10];
    const float* W_noise= (const float*)d_in[11];
    const float* W_coord= (const float*)d_in[12];
    float* out = (float*)d_out;

    float* p_in     = (float*)symaddr(g_in);
    float* p_t0     = (float*)symaddr(g_t0);
    float* p_cat    = (float*)symaddr(g_cat);
    float* p_hs     = (float*)symaddr(g_hs);
    float* p_msg    = (float*)symaddr(g_msg);
    float* p_states = (float*)symaddr(g_states);
    float* p_out    = (float*)symaddr(g_out);
    int*   p_idx    = (int*)symaddr(g_idx);
    float* p_ed     = (float*)symaddr(g_ed);
    float* p_rbf    = (float*)symaddr(g_rbf);

    dim3 gg(DD / GBN, NN / GBM);   // (4, 32)

    // 1. build concat input
    build_in_kernel<<<NN, 128>>>(feat, pos, mask, tptr, p_in);
    // 2. h = layernorm(in @ W_in) * mask ; h -> g_cat[:, :256] and states[0]
    mma_gemm_kernel<<<gg, 256>>>(p_in, W_in, p_t0, NN, DD, CIN, CIN, DD);
    ln_kernel<<<NN, DD>>>(p_t0, p_cat, 2 * DD, mask, p_states, 0);
    // 3. kNN + RBF
    knn_kernel<<<NN, 256>>>(coord, p_idx, p_ed);
    rbf_kernel<<<(NN * KK * BB + 255) / 256, 256>>>(p_ed, p_rbf);

    for (int l = 0; l < LL; l++) {
        const float* Wself_l = W_self + (size_t)l * DD * DD;
        const float* Wrad_l  = W_rad  + (size_t)l * BB * DD;
        const float* Wconv_l = W_conv + (size_t)l * DD * DD;
        const float* Wcat_l  = W_cat  + (size_t)l * 2 * DD * DD;

        // hs = layernorm(h @ W_self[l]) ; h lives in g_cat[:, :256] (lda=512)
        mma_gemm_kernel<<<gg, 256>>>(p_cat, Wself_l, p_t0, NN, DD, DD, 2 * DD, DD);
        ln_kernel<<<NN, DD>>>(p_t0, p_hs, DD, nullptr, nullptr, 0);
        // msg = mean_k( hs[idx] * (rbf @ W_rad[l]) )
        msg_kernel<<<NN, DD>>>(p_hs, p_idx, p_rbf, Wrad_l, p_msg);
        // agg = msg @ W_conv[l] -> g_cat[:, 256:512]
        mma_gemm_kernel<<<gg, 256>>>(p_msg, Wconv_l, p_cat + DD, NN, DD, DD, DD, 2 * DD);
        // t0 = [h | agg] @ W_cat[l]   (single Kd=512 GEMM)
        mma_gemm_kernel<<<gg, 256>>>(p_cat, Wcat_l, p_t0, NN, DD, 2 * DD, 2 * DD, DD);
        // h = layernorm(t0) * mask -> g_cat[:, :256] and states[l+1]
        ln_kernel<<<NN, DD>>>(p_t0, p_cat, 2 * DD, mask, p_states, l + 1);
    }

    // out = states @ W_out  ([4096,1280] @ [1280,256])
    mma_gemm_kernel<<<gg, 256>>>(p_states, W_out, p_out, NN, DD, NSTATE * DD, NSTATE * DD, DD);
    // d_out[:, :256] = out @ W_noise  (ldc = 259, scalar epilogue path)
    mma_gemm_kernel<<<gg, 256>>>(p_out, W_noise, out, NN, DD, DD, DD, DD + 3);
    // d_out[:, 256:259] = out @ W_coord
    coord_out_kernel<<<NN, 96>>>(p_out, W_coord, out);
}

// round 5
// speedup vs baseline: 1.6431x; 1.0471x over previous
#include <cuda_runtime.h>
#include <cuda_bf16.h>
#include <math.h>

#define NN 4096
#define DD 256
#define KK 32
#define LL 4
#define TT 100
#define PP 64
#define BB 32
#define CIN 420   // T + D + P
#define NSTATE 5  // L+1

// ---------------- scratch (device globals; no allocations) ----------------
__device__ float g_in[NN * CIN];
__device__ float g_cat[NN * 2 * DD];     // [h | agg] fused concat buffer (ld 512)
__device__ float g_hs[NN * DD];          // layernorm(h @ W_self)
__device__ float g_msg[NN * DD];         // mean message
__device__ float g_states[NN * NSTATE * DD];
__device__ float g_out[NN * DD];         // states @ W_out
__device__ int   g_idx[NN * KK];
__device__ float g_ed[NN * KK];
__device__ float g_rbf[NN * KK * BB];
__device__ float g_sx[NN], g_sy[NN], g_sz[NN];   // SoA coords

// ---------------- helpers ----------------
__device__ __forceinline__ float f2tf(float x) {
    unsigned r;
    asm("cvt.rna.tf32.f32 %0, %1;" : "=r"(r) : "f"(x));
    return __uint_as_float(r);
}
__device__ __forceinline__ void split2(float f, unsigned& hi, unsigned& lo) {
    float h = f2tf(f);
    float l = f2tf(f - h);
    hi = __float_as_uint(h);
    lo = __float_as_uint(l);
}
__device__ __forceinline__ void mma_tf32(float& d0, float& d1, float& d2, float& d3,
                                         unsigned a0, unsigned a1, unsigned a2, unsigned a3,
                                         unsigned b0, unsigned b1) {
    asm volatile(
        "mma.sync.aligned.m16n8k8.row.col.f32.tf32.tf32.f32 "
        "{%0,%1,%2,%3}, {%4,%5,%6,%7}, {%8,%9}, {%0,%1,%2,%3};"
        : "+f"(d0), "+f"(d1), "+f"(d2), "+f"(d3)
        : "r"(a0), "r"(a1), "r"(a2), "r"(a3), "r"(b0), "r"(b1));
}

// ---------------- input build ----------------
__global__ void build_in_kernel(const float* __restrict__ feat,
                                const float* __restrict__ pos,
                                const float* __restrict__ mask,
                                const float* __restrict__ tptr,
                                float* __restrict__ out) {
    int i = blockIdx.x;
    float t = *tptr;
    float mk = mask[i];
    for (int c = threadIdx.x; c < CIN; c += blockDim.x) {
        float v;
        if (c < TT) {
            float d = (t - (float)c * (1.0f / 99.0f)) * 99.0f;
            float a = fabsf(d);
            if (a < 1.0f) {
                float cc = cospif(0.5f * d);
                v = cc * cc * mk;
            } else v = 0.0f;
        } else if (c < TT + DD) {
            v = feat[i * DD + (c - TT)];
        } else {
            v = pos[i * PP + (c - TT - DD)];
        }
        out[i * CIN + c] = v;
    }
}

// ---------------- SoA coord transpose ----------------
__global__ void soa_kernel(const float* __restrict__ coord,
                           float* __restrict__ gx, float* __restrict__ gy,
                           float* __restrict__ gz) {
    int j = blockIdx.x * 256 + threadIdx.x;
    if (j < NN) {
        gx[j] = coord[j * 3 + 0];
        gy[j] = coord[j * 3 + 1];
        gz[j] = coord[j * 3 + 2];
    }
}

// ---------------- kNN (SoA loads) ----------------
__global__ __launch_bounds__(256) void knn_kernel(const float* __restrict__ gx,
                                                  const float* __restrict__ gy,
                                                  const float* __restrict__ gz,
                                                  int* __restrict__ idx_out,
                                                  float* __restrict__ ed_out) {
    __shared__ float dist[NN];
    __shared__ float wv[8];
    __shared__ int wi[8];
    __shared__ int s_sel;
    int i = blockIdx.x;
    int tid = threadIdx.x;
    int lane = tid & 31;
    int warp = tid >> 5;
    float cx = gx[i], cy = gy[i], cz = gz[i];
    float v = 3.4e38f;
    int bi = 0x7FFFFFFF;
    for (int j = tid; j < NN; j += 256) {
        float dx = cx - gx[j];
        float dy = cy - gy[j];
        float dz = cz - gz[j];
        float d2 = dx * dx + dy * dy + dz * dz;
        if (j == i) d2 += 1e9f;
        dist[j] = d2;
        if (d2 < v) { v = d2; bi = j; }
    }
    __syncthreads();
    for (int kk = 0; kk < KK; kk++) {
        float rv = v; int rb = bi;
        #pragma unroll
        for (int o = 16; o > 0; o >>= 1) {
            float ov = __shfl_down_sync(0xFFFFFFFFu, rv, o);
            int ob = __shfl_down_sync(0xFFFFFFFFu, rb, o);
            if (ov < rv || (ov == rv && ob < rb)) { rv = ov; rb = ob; }
        }
        if (lane == 0) { wv[warp] = rv; wi[warp] = rb; }
        __syncthreads();
        if (warp == 0) {
            float v2 = (lane < 8) ? wv[lane] : 3.4e38f;
            int b2 = (lane < 8) ? wi[lane] : 0x7FFFFFFF;
            #pragma unroll
            for (int o = 4; o > 0; o >>= 1) {
                float ov = __shfl_down_sync(0xFFFFFFFFu, v2, o);
                int ob = __shfl_down_sync(0xFFFFFFFFu, b2, o);
                if (ov < v2 || (ov == v2 && ob < b2)) { v2 = ov; b2 = ob; }
            }
            if (lane == 0) {
                idx_out[i * KK + kk] = b2;
                ed_out[i * KK + kk] = sqrtf(fmaxf(v2, 1e-12f));
                dist[b2] = 3.4e38f;
                s_sel = b2;
            }
        }
        __syncthreads();
        int b = s_sel;
        if ((b & 255) == tid) {
            v = 3.4e38f; bi = 0x7FFFFFFF;
            for (int j = tid; j < NN; j += 256) {
                float d2 = dist[j];
                if (d2 < v) { v = d2; bi = j; }
            }
        }
    }
}

// ---------------- gaussian RBF ----------------
__global__ void rbf_kernel(const float* __restrict__ ed, float* __restrict__ rbf) {
    int t = blockIdx.x * blockDim.x + threadIdx.x;
    if (t >= NN * KK * BB) return;
    int b = t & (BB - 1);
    int ik = t >> 5;
    float d = ed[ik];
    float c = 32.0f * (float)b * (1.0f / 31.0f);
    float x = d - c;
    rbf[t] = expf(-x * x);
}

// ================= fused GEMM(+LN) kernel =================
// Block tile 32x256 (full output rows), BK=32, 8 warps, warp tile 32x32.
// Split-tf32: each operand split hi/lo, 3 MMAs -> fp32-class accuracy.
#define GBK 32
#define AST 36    // As[row][k]  stride (bank-conflict-free frag loads)
#define BST 264   // Bs[k][n]    stride

template <bool DO_LN>
__global__ __launch_bounds__(256) void gemm_ln_kernel(const float* __restrict__ A,
                                                      const float* __restrict__ Bm,
                                                      float* __restrict__ C,
                                                      int Kd, int lda, int ldc,
                                                      const float* __restrict__ mask,
                                                      float* __restrict__ states,
                                                      int state_col) {
    __shared__ float As[32 * AST];
    __shared__ float Bs[32 * BST];
    int tid = threadIdx.x;
    int bm = blockIdx.x * 32;
    int warp = tid >> 5, lane = tid & 31;
    int gid = lane >> 2, tig = lane & 3;

    const float* Abase = A + (size_t)bm * lda;

    float4 avr;      // A prefetch: 1 float4/thread (32x32 tile)
    float4 bvr[8];   // B prefetch: 8 float4/thread (32x256 tile)

    // A tile: thread -> row tid>>3, k-offset (tid&7)*4
    int ar = tid >> 3;
    int ac4 = (tid & 7) * 4;

    auto load_tile = [&](int k0) {
        const float* p = Abase + (size_t)ar * lda + k0 + ac4;
        if (k0 + ac4 + 4 <= Kd) {
            avr = *reinterpret_cast<const float4*>(p);
        } else {
            float x0 = (k0 + ac4 + 0 < Kd) ? p[0] : 0.0f;
            float x1 = (k0 + ac4 + 1 < Kd) ? p[1] : 0.0f;
            float x2 = (k0 + ac4 + 2 < Kd) ? p[2] : 0.0f;
            float x3 = (k0 + ac4 + 3 < Kd) ? p[3] : 0.0f;
            avr = make_float4(x0, x1, x2, x3);
        }
        #pragma unroll
        for (int it = 0; it < 8; it++) {
            int idx = it * 256 + tid;
            int r = idx >> 6;              // k row 0..31
            int c4 = (idx & 63) * 4;       // col 0..252
            if (k0 + r < Kd) {
                bvr[it] = *reinterpret_cast<const float4*>(Bm + (size_t)(k0 + r) * DD + c4);
            } else {
                bvr[it] = make_float4(0.f, 0.f, 0.f, 0.f);
            }
        }
    };
    auto store_tile = [&]() {
        *reinterpret_cast<float4*>(&As[ar * AST + ac4]) = avr;
        #pragma unroll
        for (int it = 0; it < 8; it++) {
            int idx = it * 256 + tid;
            int r = idx >> 6;
            int c4 = (idx & 63) * 4;
            *reinterpret_cast<float4*>(&Bs[r * BST + c4]) = bvr[it];
        }
    };

    float cf[2][4][4];
    #pragma unroll
    for (int mt = 0; mt < 2; mt++)
        #pragma unroll
        for (int nt = 0; nt < 4; nt++)
            #pragma unroll
            for (int q = 0; q < 4; q++) cf[mt][nt][q] = 0.0f;

    load_tile(0);
    store_tile();
    __syncthreads();

    for (int k0 = 0;;) {
        int knext = k0 + GBK;
        bool has_next = knext < Kd;
        if (has_next) load_tile(knext);
        #pragma unroll
        for (int ks = 0; ks < 4; ks++) {
            int kc = ks * 8 + tig;
            unsigned ahi[2][4], alo[2][4];
            #pragma unroll
            for (int mt = 0; mt < 2; mt++) {
                int r = gid + mt * 16;
                split2(As[r * AST + kc],            ahi[mt][0], alo[mt][0]);
                split2(As[(r + 8) * AST + kc],      ahi[mt][1], alo[mt][1]);
                split2(As[r * AST + kc + 4],        ahi[mt][2], alo[mt][2]);
                split2(As[(r + 8) * AST + kc + 4],  ahi[mt][3], alo[mt][3]);
            }
            unsigned bhi[4][2], blo[4][2];
            #pragma unroll
            for (int nt = 0; nt < 4; nt++) {
                int cb = warp * 32 + nt * 8 + gid;
                split2(Bs[(ks * 8 + tig) * BST + cb],     bhi[nt][0], blo[nt][0]);
                split2(Bs[(ks * 8 + tig + 4) * BST + cb], bhi[nt][1], blo[nt][1]);
            }
            #pragma unroll
            for (int mt = 0; mt < 2; mt++)
                #pragma unroll
                for (int nt = 0; nt < 4; nt++) {
                    mma_tf32(cf[mt][nt][0], cf[mt][nt][1], cf[mt][nt][2], cf[mt][nt][3],
                             ahi[mt][0], ahi[mt][1], ahi[mt][2], ahi[mt][3],
                             bhi[nt][0], bhi[nt][1]);
                    mma_tf32(cf[mt][nt][0], cf[mt][nt][1], cf[mt][nt][2], cf[mt][nt][3],
                             ahi[mt][0], ahi[mt][1], ahi[mt][2], ahi[mt][3],
                             blo[nt][0], blo[nt][1]);
                    mma_tf32(cf[mt][nt][0], cf[mt][nt][1], cf[mt][nt][2], cf[mt][nt][3],
                             alo[mt][0], alo[mt][1], alo[mt][2], alo[mt][3],
                             bhi[nt][0], bhi[nt][1]);
                }
        }
        if (!has_next) break;
        __syncthreads();
        store_tile();
        __syncthreads();
        k0 = knext;
    }

    if (!DO_LN) {
        // direct store
        if ((ldc & 1) == 0) {
            #pragma unroll
            for (int mt = 0; mt < 2; mt++)
                #pragma unroll
                for (int nt = 0; nt < 4; nt++) {
                    int r0 = bm + gid + mt * 16;
                    int c = warp * 32 + nt * 8 + tig * 2;
                    *reinterpret_cast<float2*>(C + (size_t)r0 * ldc + c) =
                        make_float2(cf[mt][nt][0], cf[mt][nt][1]);
                    *reinterpret_cast<float2*>(C + (size_t)(r0 + 8) * ldc + c) =
                        make_float2(cf[mt][nt][2], cf[mt][nt][3]);
                }
        } else {
            #pragma unroll
            for (int mt = 0; mt < 2; mt++)
                #pragma unroll
                for (int nt = 0; nt < 4; nt++) {
                    int r0 = bm + gid + mt * 16;
                    int c = warp * 32 + nt * 8 + tig * 2;
                    C[(size_t)r0 * ldc + c]           = cf[mt][nt][0];
                    C[(size_t)r0 * ldc + c + 1]       = cf[mt][nt][1];
                    C[(size_t)(r0 + 8) * ldc + c]     = cf[mt][nt][2];
                    C[(size_t)(r0 + 8) * ldc + c + 1] = cf[mt][nt][3];
                }
        }
        return;
    }

    // ---- LN epilogue: stage rows in smem, normalize, store ----
    __syncthreads();   // done reading Bs
    #pragma unroll
    for (int mt = 0; mt < 2; mt++)
        #pragma unroll
        for (int nt = 0; nt < 4; nt++) {
            int r = gid + mt * 16;
            int c = warp * 32 + nt * 8 + tig * 2;
            Bs[r * BST + c]           = cf[mt][nt][0];
            Bs[r * BST + c + 1]       = cf[mt][nt][1];
            Bs[(r + 8) * BST + c]     = cf[mt][nt][2];
            Bs[(r + 8) * BST + c + 1] = cf[mt][nt][3];
        }
    __syncthreads();

    int row = tid >> 3;          // 0..31
    int sub = tid & 7;           // 0..7
    float s = 0.0f, s2 = 0.0f;
    #pragma unroll
    for (int j = 0; j < 32; j++) {
        float x = Bs[row * BST + sub + j * 8];
        s += x;
        s2 += x * x;
    }
    #pragma unroll
    for (int o = 4; o > 0; o >>= 1) {
        s  += __shfl_xor_sync(0xFFFFFFFFu, s, o);
        s2 += __shfl_xor_sync(0xFFFFFFFFu, s2, o);
    }
    float mean = s * (1.0f / DD);
    float var = s2 * (1.0f / DD) - mean * mean;
    float scale = rsqrtf(var + 1e-5f);
    int i = bm + row;
    float mk = mask ? mask[i] : 1.0f;
    float* yrow = C + (size_t)i * ldc;
    float* srow = states ? states + (size_t)i * (NSTATE * DD) + state_col * DD : nullptr;
    #pragma unroll
    for (int j = 0; j < 32; j++) {
        int c = sub + j * 8;
        float y = (Bs[row * BST + c] - mean) * scale * mk;
        yrow[c] = y;
        if (srow) srow[c] = y;
    }
}

// ================= tensor-core message kernel =================
// Per node i: EW = RS[32,32] @ Wrad[32,256] (split-tf32), then
// msg[i,:] = (1/32) * sum_k h[idx[i,k],:] * EW[k,:]
__global__ __launch_bounds__(256) void msg_mma_kernel(const float* __restrict__ h,
                                                      const int* __restrict__ idx,
                                                      const float* __restrict__ rbf,
                                                      const float* __restrict__ Wrad,
                                                      float* __restrict__ out) {
    __shared__ float As[32 * AST];    // RS
    __shared__ float Bs[32 * BST];    // Wrad, then gathered H
    __shared__ int js[KK];
    int i = blockIdx.x;
    int tid = threadIdx.x;
    int warp = tid >> 5, lane = tid & 31;
    int gid = lane >> 2, tig = lane & 3;

    // load RS [k][b] (1024 floats, 1 float4/thread)
    {
        int r = tid >> 3;
        int b4 = (tid & 7) * 4;
        *reinterpret_cast<float4*>(&As[r * AST + b4]) =
            *reinterpret_cast<const float4*>(rbf + (size_t)i * (KK * BB) + r * BB + b4);
    }
    // load Wrad [b][d] (8192 floats, 8 float4/thread)
    #pragma unroll
    for (int it = 0; it < 8; it++) {
        int idx2 = it * 256 + tid;
        int r = idx2 >> 6;
        int c4 = (idx2 & 63) * 4;
        *reinterpret_cast<float4*>(&Bs[r * BST + c4]) =
            *reinterpret_cast<const float4*>(Wrad + (size_t)r * DD + c4);
    }
    if (tid < KK) js[tid] = idx[i * KK + tid];
    __syncthreads();

    float cf[2][4][4];
    #pragma unroll
    for (int mt = 0; mt < 2; mt++)
        #pragma unroll
        for (int nt = 0; nt < 4; nt++)
            #pragma unroll
            for (int q = 0; q < 4; q++) cf[mt][nt][q] = 0.0f;

    #pragma unroll
    for (int ks = 0; ks < 4; ks++) {
        int kc = ks * 8 + tig;
        unsigned ahi[2][4], alo[2][4];
        #pragma unroll
        for (int mt = 0; mt < 2; mt++) {
            int r = gid + mt * 16;
            split2(As[r * AST + kc],            ahi[mt][0], alo[mt][0]);
            split2(As[(r + 8) * AST + kc],      ahi[mt][1], alo[mt][1]);
            split2(As[r * AST + kc + 4],        ahi[mt][2], alo[mt][2]);
            split2(As[(r + 8) * AST + kc + 4],  ahi[mt][3], alo[mt][3]);
        }
        unsigned bhi[4][2], blo[4][2];
        #pragma unroll
        for (int nt = 0; nt < 4; nt++) {
            int cb = warp * 32 + nt * 8 + gid;
            split2(Bs[(ks * 8 + tig) * BST + cb],     bhi[nt][0], blo[nt][0]);
            split2(Bs[(ks * 8 + tig + 4) * BST + cb], bhi[nt][1], blo[nt][1]);
        }
        #pragma unroll
        for (int mt = 0; mt < 2; mt++)
            #pragma unroll
            for (int nt = 0; nt < 4; nt++) {
                mma_tf32(cf[mt][nt][0], cf[mt][nt][1], cf[mt][nt][2], cf[mt][nt][3],
                         ahi[mt][0], ahi[mt][1], ahi[mt][2], ahi[mt][3],
                         bhi[nt][0], bhi[nt][1]);
                mma_tf32(cf[mt][nt][0], cf[mt][nt][1], cf[mt][nt][2], cf[mt][nt][3],
                         ahi[mt][0], ahi[mt][1], ahi[mt][2], ahi[mt][3],
                         blo[nt][0], blo[nt][1]);
                mma_tf32(cf[mt][nt][0], cf[mt][nt][1], cf[mt][nt][2], cf[mt][nt][3],
                         alo[mt][0], alo[mt][1], alo[mt][2], alo[mt][3],
                         bhi[nt][0], bhi[nt][1]);
            }
    }
    __syncthreads();   // done with Wrad in Bs

    // gather H rows into Bs: Bs[k][d] = h[js[k]][d]
    #pragma unroll
    for (int it = 0; it < 8; it++) {
        int idx2 = it * 256 + tid;
        int r = idx2 >> 6;             // k row
        int c4 = (idx2 & 63) * 4;
        int j = js[r];
        *reinterpret_cast<float4*>(&Bs[r * BST + c4]) =
            *reinterpret_cast<const float4*>(h + (size_t)j * DD + c4);
    }
    __syncthreads();

    // multiply + reduce over k (rows)
    float sacc[4][2];
    #pragma unroll
    for (int nt = 0; nt < 4; nt++) { sacc[nt][0] = 0.0f; sacc[nt][1] = 0.0f; }
    #pragma unroll
    for (int mt = 0; mt < 2; mt++) {
        int r = gid + mt * 16;
        #pragma unroll
        for (int nt = 0; nt < 4; nt++) {
            int c = warp * 32 + nt * 8 + tig * 2;
            sacc[nt][0] += cf[mt][nt][0] * Bs[r * BST + c];
            sacc[nt][1] += cf[mt][nt][1] * Bs[r * BST + c + 1];
            sacc[nt][0] += cf[mt][nt][2] * Bs[(r + 8) * BST + c];
            sacc[nt][1] += cf[mt][nt][3] * Bs[(r + 8) * BST + c + 1];
        }
    }
    #pragma unroll
    for (int o = 4; o <= 16; o <<= 1) {
        #pragma unroll
        for (int nt = 0; nt < 4; nt++) {
            sacc[nt][0] += __shfl_xor_sync(0xFFFFFFFFu, sacc[nt][0], o);
            sacc[nt][1] += __shfl_xor_sync(0xFFFFFFFFu, sacc[nt][1], o);
        }
    }
    if (gid == 0) {
        #pragma unroll
        for (int nt = 0; nt < 4; nt++) {
            int c = warp * 32 + nt * 8 + tig * 2;
            out[(size_t)i * DD + c]     = sacc[nt][0] * (1.0f / KK);
            out[(size_t)i * DD + c + 1] = sacc[nt][1] * (1.0f / KK);
        }
    }
}

// ---------------- coord head ----------------
__global__ void coord_out_kernel(const float* __restrict__ out,
                                 const float* __restrict__ Wc,
                                 float* __restrict__ dout) {
    int i = blockIdx.x;
    int w = threadIdx.x >> 5, lane = threadIdx.x & 31;
    float s = 0.0f;
    for (int d = lane; d < DD; d += 32) s += out[i * DD + d] * Wc[d * 3 + w];
    #pragma unroll
    for (int o = 16; o > 0; o >>= 1) s += __shfl_down_sync(0xFFFFFFFFu, s, o);
    if (lane == 0) dout[(size_t)i * (DD + 3) + DD + w] = s;
}

// ---------------- host launcher ----------------
static void* symaddr(const void* s) {
    void* p = nullptr;
    cudaGetSymbolAddress(&p, s);
    return p;
}

extern "C" void kernel_launch(void* const* d_in, const int* in_sizes, int n_in,
                              void* d_out, int out_size) {
    const float* feat   = (const float*)d_in[0];
    const float* coord  = (const float*)d_in[1];
    const float* mask   = (const float*)d_in[2];
    const float* tptr   = (const float*)d_in[3];
    const float* pos    = (const float*)d_in[4];
    const float* W_in   = (const float*)d_in[5];
    const float* W_self = (const float*)d_in[6];
    const float* W_rad  = (const float*)d_in[7];
    const float* W_conv = (const float*)d_in[8];
    const float* W_cat  = (const float*)d_in[9];
    const float* W_out  = (const float*)d_in[10];
    const float* W_noise= (const float*)d_in[11];
    const float* W_coord= (const float*)d_in[12];
    float* out = (float*)d_out;

    float* p_in     = (float*)symaddr(g_in);
    float* p_cat    = (float*)symaddr(g_cat);
    float* p_hs     = (float*)symaddr(g_hs);
    float* p_msg    = (float*)symaddr(g_msg);
    float* p_states = (float*)symaddr(g_states);
    float* p_out    = (float*)symaddr(g_out);
    int*   p_idx    = (int*)symaddr(g_idx);
    float* p_ed     = (float*)symaddr(g_ed);
    float* p_rbf    = (float*)symaddr(g_rbf);
    float* p_sx     = (float*)symaddr(g_sx);
    float* p_sy     = (float*)symaddr(g_sy);
    float* p_sz     = (float*)symaddr(g_sz);

    int gg = NN / 32;   // 128 blocks

    build_in_kernel<<<NN, 128>>>(feat, pos, mask, tptr, p_in);
    // h = LN(in @ W_in) * mask -> g_cat[:, :256] (ld 512), states[0]
    gemm_ln_kernel<true><<<gg, 256>>>(p_in, W_in, p_cat, CIN, CIN, 2 * DD,
                                      mask, p_states, 0);
    soa_kernel<<<NN / 256, 256>>>(coord, p_sx, p_sy, p_sz);
    knn_kernel<<<NN, 256>>>(p_sx, p_sy, p_sz, p_idx, p_ed);
    rbf_kernel<<<(NN * KK * BB + 255) / 256, 256>>>(p_ed, p_rbf);

    for (int l = 0; l < LL; l++) {
        const float* Wself_l = W_self + (size_t)l * DD * DD;
        const float* Wrad_l  = W_rad  + (size_t)l * BB * DD;
        const float* Wconv_l = W_conv + (size_t)l * DD * DD;
        const float* Wcat_l  = W_cat  + (size_t)l * 2 * DD * DD;

        // hs = LN(h @ W_self[l])   (h in g_cat[:, :256], lda 512)
        gemm_ln_kernel<true><<<gg, 256>>>(p_cat, Wself_l, p_hs, DD, 2 * DD, DD,
                                          nullptr, nullptr, 0);
        // msg = mean_k( hs[idx] * (rbf @ W_rad[l]) )
        msg_mma_kernel<<<NN, 256>>>(p_hs, p_idx, p_rbf, Wrad_l, p_msg);
        // agg = msg @ W_conv[l] -> g_cat[:, 256:512]
        gemm_ln_kernel<false><<<gg, 256>>>(p_msg, Wconv_l, p_cat + DD, DD, DD, 2 * DD,
                                           nullptr, nullptr, 0);
        // h = LN([h|agg] @ W_cat[l]) * mask -> g_cat[:, :256], states[l+1]
        gemm_ln_kernel<true><<<gg, 256>>>(p_cat, Wcat_l, p_cat, 2 * DD, 2 * DD, 2 * DD,
                                          mask, p_states, l + 1);
    }

    // out = states @ W_out
    gemm_ln_kernel<false><<<gg, 256>>>(p_states, W_out, p_out, NSTATE * DD, NSTATE * DD, DD,
                                       nullptr, nullptr, 0);
    // d_out[:, :256] = out @ W_noise (ldc = 259, scalar store path)
    gemm_ln_kernel<false><<<gg, 256>>>(p_out, W_noise, out, DD, DD, DD + 3,
                                       nullptr, nullptr, 0);
    // d_out[:, 256:259] = out @ W_coord
    coord_out_kernel<<<NN, 96>>>(p_out, W_coord, out);
}